// round 1
// baseline (speedup 1.0000x reference)
#include <cuda_runtime.h>

// LSTM: B=32768, T=28, IN=28, H=8, gates order i,j,f,o; FORGET_BIAS=1.0
// Strategy: 1 batch element per thread. Gate columns (g, g+16) packed into
// f32x2 lanes -> fma.rn.f32x2 halves FMA-pipe work. W pre-packed in smem as
// ulonglong2 (LDS.128 broadcast). x prefetched one step ahead (float4).

#define T_STEPS 28
#define IN_DIM 28
#define NH 8
#define NC 10
#define TPB 64

typedef unsigned long long u64;

__device__ __forceinline__ u64 pack2(float lo, float hi) {
    u64 r;
    asm("mov.b64 %0, {%1, %2};" : "=l"(r) : "f"(lo), "f"(hi));
    return r;
}
__device__ __forceinline__ void unpack2(u64 v, float& lo, float& hi) {
    asm("mov.b64 {%0, %1}, %2;" : "=f"(lo), "=f"(hi) : "l"(v));
}
__device__ __forceinline__ u64 fma2(u64 a, u64 b, u64 c) {
    u64 d;
    asm("fma.rn.f32x2 %0, %1, %2, %3;" : "=l"(d) : "l"(a), "l"(b), "l"(c));
    return d;
}
__device__ __forceinline__ float rcp_fast(float x) {
    float r;
    asm("rcp.approx.ftz.f32 %0, %1;" : "=f"(r) : "f"(x));
    return r;
}
__device__ __forceinline__ float ex2_fast(float x) {
    float r;
    asm("ex2.approx.ftz.f32 %0, %1;" : "=f"(r) : "f"(x));
    return r;
}

#define LOG2E 1.4426950408889634f

// sigmoid(x) = 1 / (1 + 2^(-x*log2e))   (ex2 + rcp, ~1e-6 rel err)
__device__ __forceinline__ float sigmoid_f(float x) {
    return rcp_fast(1.0f + ex2_fast(-x * LOG2E));
}
// tanh(x) = 1 - 2 / (2^(2x*log2e) + 1)
__device__ __forceinline__ float tanh_f(float x) {
    return 1.0f - 2.0f * rcp_fast(1.0f + ex2_fast(2.0f * LOG2E * x));
}

__global__ void __launch_bounds__(TPB)
lstm_kernel(const float* __restrict__ x,
            const float* __restrict__ W,     // [36, 32]
            const float* __restrict__ b,     // [32]
            const float* __restrict__ ow,    // [8, 10]
            const float* __restrict__ ob,    // [10]
            float* __restrict__ out,         // [B, 10]
            int B)
{
    // Packed weights: sW[k*16 + g] = (W[k][g], W[k][g+16]), g in [0,16)
    __shared__ __align__(16) u64 sW[36 * 16];
    __shared__ u64 sB[16];
    __shared__ float sOw[NH * NC];
    __shared__ float sOb[NC];

    const int tid = threadIdx.x;

    for (int idx = tid; idx < 36 * 16; idx += TPB) {
        int k = idx >> 4, g = idx & 15;
        sW[idx] = pack2(W[k * 32 + g], W[k * 32 + g + 16]);
    }
    if (tid < 16) {
        // hi half is f-gate (g<8, gets FORGET_BIAS) or o-gate (g>=8)
        float hi = b[tid + 16] + (tid < 8 ? 1.0f : 0.0f);
        sB[tid] = pack2(b[tid], hi);
    }
    for (int idx = tid; idx < NH * NC; idx += TPB) sOw[idx] = ow[idx];
    if (tid < NC) sOb[tid] = ob[tid];
    __syncthreads();

    const int elem = blockIdx.x * TPB + tid;
    if (elem >= B) return;

    const float4* __restrict__ xin =
        reinterpret_cast<const float4*>(x + (size_t)elem * (T_STEPS * IN_DIM));

    float c[NH], h[NH];
#pragma unroll
    for (int g = 0; g < NH; g++) { c[g] = 0.0f; h[g] = 0.0f; }

    // prefetch t = 0
    float4 nbuf[7];
#pragma unroll
    for (int i = 0; i < 7; i++) nbuf[i] = xin[i];

#pragma unroll 1
    for (int t = 0; t < T_STEPS; t++) {
        float xt[IN_DIM];
#pragma unroll
        for (int i = 0; i < 7; i++)
            reinterpret_cast<float4*>(xt)[i] = nbuf[i];

        // prefetch next step (clamped: last iter redoes t=27, always in-bounds)
        const int tn = (t < T_STEPS - 1) ? t + 1 : t;
#pragma unroll
        for (int i = 0; i < 7; i++) nbuf[i] = xin[tn * 7 + i];

        u64 acc[16];
#pragma unroll
        for (int g = 0; g < 16; g++) acc[g] = sB[g];

        // x contribution: 28 x 16 packed FMAs
#pragma unroll
        for (int k = 0; k < IN_DIM; k++) {
            u64 xp = pack2(xt[k], xt[k]);
            const ulonglong2* wr =
                reinterpret_cast<const ulonglong2*>(&sW[k * 16]);
#pragma unroll
            for (int p = 0; p < 8; p++) {
                ulonglong2 w = wr[p];
                acc[2 * p]     = fma2(xp, w.x, acc[2 * p]);
                acc[2 * p + 1] = fma2(xp, w.y, acc[2 * p + 1]);
            }
        }
        // h contribution: 8 x 16 packed FMAs
#pragma unroll
        for (int k = 0; k < NH; k++) {
            u64 hp = pack2(h[k], h[k]);
            const ulonglong2* wr =
                reinterpret_cast<const ulonglong2*>(&sW[(IN_DIM + k) * 16]);
#pragma unroll
            for (int p = 0; p < 8; p++) {
                ulonglong2 w = wr[p];
                acc[2 * p]     = fma2(hp, w.x, acc[2 * p]);
                acc[2 * p + 1] = fma2(hp, w.y, acc[2 * p + 1]);
            }
        }

        // activations + state update (pairs: acc[g]=(i_g, f_g), acc[8+g]=(j_g, o_g))
#pragma unroll
        for (int g = 0; g < NH; g++) {
            float ai, af, aj, ao;
            unpack2(acc[g], ai, af);
            unpack2(acc[8 + g], aj, ao);
            float is = sigmoid_f(ai);
            float fs = sigmoid_f(af);   // FORGET_BIAS already in bias
            float jt = tanh_f(aj);
            float os = sigmoid_f(ao);
            float cn = c[g] * fs + is * jt;
            c[g] = cn;
            h[g] = tanh_f(cn) * os;
        }
    }

    // output projection
    float* __restrict__ po = out + (size_t)elem * NC;
#pragma unroll
    for (int cls = 0; cls < NC; cls++) {
        float a = sOb[cls];
#pragma unroll
        for (int k = 0; k < NH; k++) a += h[k] * sOw[k * NC + cls];
        po[cls] = a;
    }
}

extern "C" void kernel_launch(void* const* d_in, const int* in_sizes, int n_in,
                              void* d_out, int out_size) {
    const float* x  = (const float*)d_in[0];
    const float* W  = (const float*)d_in[1];
    const float* b  = (const float*)d_in[2];
    const float* ow = (const float*)d_in[3];
    const float* ob = (const float*)d_in[4];
    float* out = (float*)d_out;

    const int B = in_sizes[0] / (T_STEPS * IN_DIM);
    const int grid = (B + TPB - 1) / TPB;
    lstm_kernel<<<grid, TPB>>>(x, W, b, ow, ob, out, B);
}

// round 2
// speedup vs baseline: 1.0326x; 1.0326x over previous
#include <cuda_runtime.h>

// LSTM: B=32768, T=28, IN=28, H=8, gates i,j,f,o; FORGET_BIAS=1.0
// One batch element per thread. Gate pairs (g, g+16) packed into f32x2 ->
// fma.rn.f32x2 halves FMA-pipe work. W pre-packed in smem (LDS.128 broadcast).
// R2 fix: no local arrays taken by address (R1 spilled: 255 regs, 3.3GB local
// traffic). x loaded as 7 float4 regs, launch_bounds caps regs at 128.

#define T_STEPS 28
#define IN_DIM 28
#define NH 8
#define NC 10
#define TPB 64

typedef unsigned long long u64;

__device__ __forceinline__ u64 pack2(float lo, float hi) {
    u64 r;
    asm("mov.b64 %0, {%1, %2};" : "=l"(r) : "f"(lo), "f"(hi));
    return r;
}
__device__ __forceinline__ void unpack2(u64 v, float& lo, float& hi) {
    asm("mov.b64 {%0, %1}, %2;" : "=f"(lo), "=f"(hi) : "l"(v));
}
__device__ __forceinline__ u64 fma2(u64 a, u64 b, u64 c) {
    u64 d;
    asm("fma.rn.f32x2 %0, %1, %2, %3;" : "=l"(d) : "l"(a), "l"(b), "l"(c));
    return d;
}
__device__ __forceinline__ float rcp_fast(float x) {
    float r;
    asm("rcp.approx.ftz.f32 %0, %1;" : "=f"(r) : "f"(x));
    return r;
}
__device__ __forceinline__ float ex2_fast(float x) {
    float r;
    asm("ex2.approx.ftz.f32 %0, %1;" : "=f"(r) : "f"(x));
    return r;
}

#define LOG2E 1.4426950408889634f

__device__ __forceinline__ float sigmoid_f(float x) {
    return rcp_fast(1.0f + ex2_fast(-x * LOG2E));
}
__device__ __forceinline__ float tanh_f(float x) {
    return 1.0f - 2.0f * rcp_fast(1.0f + ex2_fast(2.0f * LOG2E * x));
}

// 16 packed FMAs: acc[g] += (v,v) * sWrow[g]
__device__ __forceinline__ void gate_fma(u64* acc, const u64* sWrow, float v) {
    u64 xp = pack2(v, v);
    const ulonglong2* wr = reinterpret_cast<const ulonglong2*>(sWrow);
#pragma unroll
    for (int p = 0; p < 8; p++) {
        ulonglong2 w = wr[p];
        acc[2 * p]     = fma2(xp, w.x, acc[2 * p]);
        acc[2 * p + 1] = fma2(xp, w.y, acc[2 * p + 1]);
    }
}

__global__ void __launch_bounds__(TPB, 8)
lstm_kernel(const float* __restrict__ x,
            const float* __restrict__ W,     // [36, 32]
            const float* __restrict__ b,     // [32]
            const float* __restrict__ ow,    // [8, 10]
            const float* __restrict__ ob,    // [10]
            float* __restrict__ out,         // [B, 10]
            int B)
{
    // sW[k*16 + g] = (W[k][g], W[k][g+16]), g in [0,16)
    __shared__ __align__(16) u64 sW[36 * 16];
    __shared__ __align__(16) u64 sB[16];
    __shared__ float sOw[NH * NC];
    __shared__ float sOb[NC];

    const int tid = threadIdx.x;

    for (int idx = tid; idx < 36 * 16; idx += TPB) {
        int k = idx >> 4, g = idx & 15;
        sW[idx] = pack2(W[k * 32 + g], W[k * 32 + g + 16]);
    }
    if (tid < 16) {
        float hi = b[tid + 16] + (tid < 8 ? 1.0f : 0.0f);  // FORGET_BIAS in f
        sB[tid] = pack2(b[tid], hi);
    }
    for (int idx = tid; idx < NH * NC; idx += TPB) sOw[idx] = ow[idx];
    if (tid < NC) sOb[tid] = ob[tid];
    __syncthreads();

    const int elem = blockIdx.x * TPB + tid;
    if (elem >= B) return;

    const float4* __restrict__ xin =
        reinterpret_cast<const float4*>(x + (size_t)elem * (T_STEPS * IN_DIM));

    float c[NH], h[NH];
#pragma unroll
    for (int g = 0; g < NH; g++) { c[g] = 0.0f; h[g] = 0.0f; }

#pragma unroll 1
    for (int t = 0; t < T_STEPS; t++) {
        // 7 float4 loads upfront (registers, MLP=7)
        float4 xv[7];
#pragma unroll
        for (int i = 0; i < 7; i++) xv[i] = xin[t * 7 + i];

        u64 acc[16];
#pragma unroll
        for (int g = 0; g < 16; g++) acc[g] = sB[g];

        // x contribution: 28 x 16 packed FMAs, consume float4 fields directly
#pragma unroll
        for (int i = 0; i < 7; i++) {
            gate_fma(acc, &sW[(4 * i + 0) * 16], xv[i].x);
            gate_fma(acc, &sW[(4 * i + 1) * 16], xv[i].y);
            gate_fma(acc, &sW[(4 * i + 2) * 16], xv[i].z);
            gate_fma(acc, &sW[(4 * i + 3) * 16], xv[i].w);
        }
        // h contribution: 8 x 16 packed FMAs
#pragma unroll
        for (int k = 0; k < NH; k++)
            gate_fma(acc, &sW[(IN_DIM + k) * 16], h[k]);

        // acc[g] = (i_g, f_g), acc[8+g] = (j_g, o_g)
#pragma unroll
        for (int g = 0; g < NH; g++) {
            float ai, af, aj, ao;
            unpack2(acc[g], ai, af);
            unpack2(acc[8 + g], aj, ao);
            float is = sigmoid_f(ai);
            float fs = sigmoid_f(af);
            float jt = tanh_f(aj);
            float os = sigmoid_f(ao);
            float cn = c[g] * fs + is * jt;
            c[g] = cn;
            h[g] = tanh_f(cn) * os;
        }
    }

    float* __restrict__ po = out + (size_t)elem * NC;
#pragma unroll
    for (int cls = 0; cls < NC; cls++) {
        float a = sOb[cls];
#pragma unroll
        for (int k = 0; k < NH; k++) a += h[k] * sOw[k * NC + cls];
        po[cls] = a;
    }
}

extern "C" void kernel_launch(void* const* d_in, const int* in_sizes, int n_in,
                              void* d_out, int out_size) {
    const float* x  = (const float*)d_in[0];
    const float* W  = (const float*)d_in[1];
    const float* b  = (const float*)d_in[2];
    const float* ow = (const float*)d_in[3];
    const float* ob = (const float*)d_in[4];
    float* out = (float*)d_out;

    const int B = in_sizes[0] / (T_STEPS * IN_DIM);
    const int grid = (B + TPB - 1) / TPB;
    lstm_kernel<<<grid, TPB>>>(x, W, b, ow, ob, out, B);
}

// round 3
// speedup vs baseline: 1.1878x; 1.1504x over previous
#include <cuda_runtime.h>

// LSTM: B=32768, T=28, IN=28, H=8, gates i,j,f,o; FORGET_BIAS=1.0
// One batch element per thread. Gate pairs (g, g+16) packed into f32x2 ->
// fma.rn.f32x2 halves FMA-pipe work. W pre-packed in smem (LDS.128 broadcast).
// R3 fix: R2's __launch_bounds__(64,8) capped regs at 128 -> ptxas spilled
// (4.3GB local traffic, fma 3.8%). Live state ~120+ regs. Occupancy is
// grid-limited (512 CTAs / 148 SMs), NOT reg-limited, so cap at 255 instead.

#define T_STEPS 28
#define IN_DIM 28
#define NH 8
#define NC 10
#define TPB 64

typedef unsigned long long u64;

__device__ __forceinline__ u64 pack2(float lo, float hi) {
    u64 r;
    asm("mov.b64 %0, {%1, %2};" : "=l"(r) : "f"(lo), "f"(hi));
    return r;
}
__device__ __forceinline__ void unpack2(u64 v, float& lo, float& hi) {
    asm("mov.b64 {%0, %1}, %2;" : "=f"(lo), "=f"(hi) : "l"(v));
}
__device__ __forceinline__ u64 fma2(u64 a, u64 b, u64 c) {
    u64 d;
    asm("fma.rn.f32x2 %0, %1, %2, %3;" : "=l"(d) : "l"(a), "l"(b), "l"(c));
    return d;
}
__device__ __forceinline__ float rcp_fast(float x) {
    float r;
    asm("rcp.approx.ftz.f32 %0, %1;" : "=f"(r) : "f"(x));
    return r;
}
__device__ __forceinline__ float ex2_fast(float x) {
    float r;
    asm("ex2.approx.ftz.f32 %0, %1;" : "=f"(r) : "f"(x));
    return r;
}

#define LOG2E 1.4426950408889634f

__device__ __forceinline__ float sigmoid_f(float x) {
    return rcp_fast(1.0f + ex2_fast(-x * LOG2E));
}
__device__ __forceinline__ float tanh_f(float x) {
    return 1.0f - 2.0f * rcp_fast(1.0f + ex2_fast(2.0f * LOG2E * x));
}

// 16 packed FMAs: acc[g] += (v,v) * sWrow[g]
__device__ __forceinline__ void gate_fma(u64* acc, const u64* sWrow, float v) {
    u64 xp = pack2(v, v);
    const ulonglong2* wr = reinterpret_cast<const ulonglong2*>(sWrow);
#pragma unroll
    for (int p = 0; p < 8; p++) {
        ulonglong2 w = wr[p];
        acc[2 * p]     = fma2(xp, w.x, acc[2 * p]);
        acc[2 * p + 1] = fma2(xp, w.y, acc[2 * p + 1]);
    }
}

__global__ void __launch_bounds__(TPB, 4)   // cap 255 regs; no spills
lstm_kernel(const float* __restrict__ x,
            const float* __restrict__ W,     // [36, 32]
            const float* __restrict__ b,     // [32]
            const float* __restrict__ ow,    // [8, 10]
            const float* __restrict__ ob,    // [10]
            float* __restrict__ out,         // [B, 10]
            int B)
{
    // sW[k*16 + g] = (W[k][g], W[k][g+16]), g in [0,16)
    __shared__ __align__(16) u64 sW[36 * 16];
    __shared__ __align__(16) u64 sB[16];
    __shared__ float sOw[NH * NC];
    __shared__ float sOb[NC];

    const int tid = threadIdx.x;

    for (int idx = tid; idx < 36 * 16; idx += TPB) {
        int k = idx >> 4, g = idx & 15;
        sW[idx] = pack2(W[k * 32 + g], W[k * 32 + g + 16]);
    }
    if (tid < 16) {
        float hi = b[tid + 16] + (tid < 8 ? 1.0f : 0.0f);  // FORGET_BIAS in f
        sB[tid] = pack2(b[tid], hi);
    }
    for (int idx = tid; idx < NH * NC; idx += TPB) sOw[idx] = ow[idx];
    if (tid < NC) sOb[tid] = ob[tid];
    __syncthreads();

    const int elem = blockIdx.x * TPB + tid;
    if (elem >= B) return;

    const float4* __restrict__ xin =
        reinterpret_cast<const float4*>(x + (size_t)elem * (T_STEPS * IN_DIM));

    float c[NH], h[NH];
#pragma unroll
    for (int g = 0; g < NH; g++) { c[g] = 0.0f; h[g] = 0.0f; }

#pragma unroll 1
    for (int t = 0; t < T_STEPS; t++) {
        // 7 float4 loads upfront (registers, MLP=7)
        float4 xv[7];
#pragma unroll
        for (int i = 0; i < 7; i++) xv[i] = xin[t * 7 + i];

        u64 acc[16];
#pragma unroll
        for (int g = 0; g < 16; g++) acc[g] = sB[g];

        // x contribution: 28 x 16 packed FMAs, consume float4 fields directly
#pragma unroll
        for (int i = 0; i < 7; i++) {
            gate_fma(acc, &sW[(4 * i + 0) * 16], xv[i].x);
            gate_fma(acc, &sW[(4 * i + 1) * 16], xv[i].y);
            gate_fma(acc, &sW[(4 * i + 2) * 16], xv[i].z);
            gate_fma(acc, &sW[(4 * i + 3) * 16], xv[i].w);
        }
        // h contribution: 8 x 16 packed FMAs
#pragma unroll
        for (int k = 0; k < NH; k++)
            gate_fma(acc, &sW[(IN_DIM + k) * 16], h[k]);

        // acc[g] = (i_g, f_g), acc[8+g] = (j_g, o_g)
#pragma unroll
        for (int g = 0; g < NH; g++) {
            float ai, af, aj, ao;
            unpack2(acc[g], ai, af);
            unpack2(acc[8 + g], aj, ao);
            float is = sigmoid_f(ai);
            float fs = sigmoid_f(af);
            float jt = tanh_f(aj);
            float os = sigmoid_f(ao);
            float cn = c[g] * fs + is * jt;
            c[g] = cn;
            h[g] = tanh_f(cn) * os;
        }
    }

    float* __restrict__ po = out + (size_t)elem * NC;
#pragma unroll
    for (int cls = 0; cls < NC; cls++) {
        float a = sOb[cls];
#pragma unroll
        for (int k = 0; k < NH; k++) a += h[k] * sOw[k * NC + cls];
        po[cls] = a;
    }
}

extern "C" void kernel_launch(void* const* d_in, const int* in_sizes, int n_in,
                              void* d_out, int out_size) {
    const float* x  = (const float*)d_in[0];
    const float* W  = (const float*)d_in[1];
    const float* b  = (const float*)d_in[2];
    const float* ow = (const float*)d_in[3];
    const float* ob = (const float*)d_in[4];
    float* out = (float*)d_out;

    const int B = in_sizes[0] / (T_STEPS * IN_DIM);
    const int grid = (B + TPB - 1) / TPB;
    lstm_kernel<<<grid, TPB>>>(x, W, b, ow, ob, out, B);
}

// round 4
// speedup vs baseline: 6.9342x; 5.8377x over previous
#include <cuda_runtime.h>

// LSTM: B=32768, T=28, IN=28, H=8, gates i,j,f,o; FORGET_BIAS=1.0
// One batch element per thread. Gate pairs (g, g+16) packed into f32x2 ->
// fma.rn.f32x2 halves FMA-pipe work. W pre-packed in smem (LDS.128 broadcast).
// R4 fix: R2/R3 spilled because the fully-unrolled 576-FMA step body let
// ptxas hoist dozens of weight LDS, blowing the live-range window past 255.
// Shrink the WINDOW: unroll-1 over the 7 x-groups (manual 1-deep prefetch),
// unroll-2 over the h rows. Min live state ~90 regs -> no spills expected.

#define T_STEPS 28
#define IN_DIM 28
#define NH 8
#define NC 10
#define TPB 64

typedef unsigned long long u64;

__device__ __forceinline__ u64 pack2(float lo, float hi) {
    u64 r;
    asm("mov.b64 %0, {%1, %2};" : "=l"(r) : "f"(lo), "f"(hi));
    return r;
}
__device__ __forceinline__ void unpack2(u64 v, float& lo, float& hi) {
    asm("mov.b64 {%0, %1}, %2;" : "=f"(lo), "=f"(hi) : "l"(v));
}
__device__ __forceinline__ u64 fma2(u64 a, u64 b, u64 c) {
    u64 d;
    asm("fma.rn.f32x2 %0, %1, %2, %3;" : "=l"(d) : "l"(a), "l"(b), "l"(c));
    return d;
}
__device__ __forceinline__ float rcp_fast(float x) {
    float r;
    asm("rcp.approx.ftz.f32 %0, %1;" : "=f"(r) : "f"(x));
    return r;
}
__device__ __forceinline__ float ex2_fast(float x) {
    float r;
    asm("ex2.approx.ftz.f32 %0, %1;" : "=f"(r) : "f"(x));
    return r;
}

#define LOG2E 1.4426950408889634f

__device__ __forceinline__ float sigmoid_f(float x) {
    return rcp_fast(1.0f + ex2_fast(-x * LOG2E));
}
__device__ __forceinline__ float tanh_f(float x) {
    return 1.0f - 2.0f * rcp_fast(1.0f + ex2_fast(2.0f * LOG2E * x));
}

// 16 packed FMAs: acc[g] += (v,v) * sWrow[g]
__device__ __forceinline__ void gate_fma(u64* acc, const u64* sWrow, float v) {
    u64 xp = pack2(v, v);
    const ulonglong2* wr = reinterpret_cast<const ulonglong2*>(sWrow);
#pragma unroll
    for (int p = 0; p < 8; p++) {
        ulonglong2 w = wr[p];
        acc[2 * p]     = fma2(xp, w.x, acc[2 * p]);
        acc[2 * p + 1] = fma2(xp, w.y, acc[2 * p + 1]);
    }
}

__global__ void __launch_bounds__(TPB, 4)   // 255-reg ceiling only
lstm_kernel(const float* __restrict__ x,
            const float* __restrict__ W,     // [36, 32]
            const float* __restrict__ b,     // [32]
            const float* __restrict__ ow,    // [8, 10]
            const float* __restrict__ ob,    // [10]
            float* __restrict__ out,         // [B, 10]
            int B)
{
    // sW[k*16 + g] = (W[k][g], W[k][g+16]), g in [0,16)
    __shared__ __align__(16) u64 sW[36 * 16];
    __shared__ __align__(16) u64 sB[16];
    __shared__ float sOw[NH * NC];
    __shared__ float sOb[NC];

    const int tid = threadIdx.x;

    for (int idx = tid; idx < 36 * 16; idx += TPB) {
        int k = idx >> 4, g = idx & 15;
        sW[idx] = pack2(W[k * 32 + g], W[k * 32 + g + 16]);
    }
    if (tid < 16) {
        float hi = b[tid + 16] + (tid < 8 ? 1.0f : 0.0f);  // FORGET_BIAS in f
        sB[tid] = pack2(b[tid], hi);
    }
    for (int idx = tid; idx < NH * NC; idx += TPB) sOw[idx] = ow[idx];
    if (tid < NC) sOb[tid] = ob[tid];
    __syncthreads();

    const int elem = blockIdx.x * TPB + tid;
    if (elem >= B) return;

    const float4* __restrict__ xin =
        reinterpret_cast<const float4*>(x + (size_t)elem * (T_STEPS * IN_DIM));

    float c[NH], h[NH];
#pragma unroll
    for (int g = 0; g < NH; g++) { c[g] = 0.0f; h[g] = 0.0f; }

#pragma unroll 1
    for (int t = 0; t < T_STEPS; t++) {
        u64 acc[16];
#pragma unroll
        for (int g = 0; g < 16; g++) acc[g] = sB[g];

        // x contribution: 7 groups of 4 rows; rolled loop keeps the weight-
        // load scheduling window small. 1-deep prefetch hides LDG latency.
        float4 cur = xin[t * 7];
#pragma unroll 1
        for (int i = 0; i < 7; i++) {
            float4 nxt = (i < 6) ? xin[t * 7 + i + 1] : cur;
            gate_fma(acc, &sW[(4 * i + 0) * 16], cur.x);
            gate_fma(acc, &sW[(4 * i + 1) * 16], cur.y);
            gate_fma(acc, &sW[(4 * i + 2) * 16], cur.z);
            gate_fma(acc, &sW[(4 * i + 3) * 16], cur.w);
            cur = nxt;
        }
        // h contribution: 8 rows, partial unroll to bound the window
#pragma unroll 2
        for (int k = 0; k < NH; k++)
            gate_fma(acc, &sW[(IN_DIM + k) * 16], h[k]);

        // acc[g] = (i_g, f_g), acc[8+g] = (j_g, o_g)
#pragma unroll
        for (int g = 0; g < NH; g++) {
            float ai, af, aj, ao;
            unpack2(acc[g], ai, af);
            unpack2(acc[8 + g], aj, ao);
            float is = sigmoid_f(ai);
            float fs = sigmoid_f(af);
            float jt = tanh_f(aj);
            float os = sigmoid_f(ao);
            float cn = c[g] * fs + is * jt;
            c[g] = cn;
            h[g] = tanh_f(cn) * os;
        }
    }

    float* __restrict__ po = out + (size_t)elem * NC;
#pragma unroll
    for (int cls = 0; cls < NC; cls++) {
        float a = sOb[cls];
#pragma unroll
        for (int k = 0; k < NH; k++) a += h[k] * sOw[k * NC + cls];
        po[cls] = a;
    }
}

extern "C" void kernel_launch(void* const* d_in, const int* in_sizes, int n_in,
                              void* d_out, int out_size) {
    const float* x  = (const float*)d_in[0];
    const float* W  = (const float*)d_in[1];
    const float* b  = (const float*)d_in[2];
    const float* ow = (const float*)d_in[3];
    const float* ob = (const float*)d_in[4];
    float* out = (float*)d_out;

    const int B = in_sizes[0] / (T_STEPS * IN_DIM);
    const int grid = (B + TPB - 1) / TPB;
    lstm_kernel<<<grid, TPB>>>(x, W, b, ow, ob, out, B);
}